// round 9
// baseline (speedup 1.0000x reference)
#include <cuda_runtime.h>

#define BAG 15
#define IM 28
#define POSMAX 20
#define LAM 0.001f
#define TPB 128
#define MAXB 65536
#define MAXBLK 512
#define NPMAX 225
#define WROW 20            /* packed window row: cols 4..24 of image */
#define WIN_F (16 * WROW)  /* 320 floats per sample */

__device__ __align__(16) float g_WiT[66 * 16];   // WiT[k*16+u] = Wi[u*66+k], col 15 = 0
__device__ __align__(16) float g_reffT[16 * 16]; // [j*16+u] = Reff[u][j]
__device__ float g_state[BAG * MAXB];            // [u][b]
__device__ unsigned int g_pos[MAXB];             // r | (c<<8)
__device__ float g_partial[NPMAX * MAXBLK];      // [pair][block]
__device__ int g_pidx[NPMAX];
__device__ int g_pi[NPMAX];
__device__ int g_pj[NPMAX];
__device__ int g_np;
__device__ __align__(16) float g_win[(size_t)MAXB * WIN_F]; // packed 16x20 windows (~84MB, L2-resident)

__device__ __forceinline__ float warp_sum(float v) {
    v += __shfl_xor_sync(0xffffffffu, v, 16);
    v += __shfl_xor_sync(0xffffffffu, v, 8);
    v += __shfl_xor_sync(0xffffffffu, v, 4);
    v += __shfl_xor_sync(0xffffffffu, v, 2);
    v += __shfl_xor_sync(0xffffffffu, v, 1);
    return v;
}

// acc[0..14] += val * base[0..14]   (base 16B-aligned shared, padded to 16 floats)
#define FMA15S(val, base) do {                                             \
    const float4* _wp = (const float4*)(base);                             \
    float4 _w0 = _wp[0], _w1 = _wp[1], _w2 = _wp[2], _w3 = _wp[3];         \
    float _v = (val);                                                      \
    acc[0]  = fmaf(_v, _w0.x, acc[0]);  acc[1]  = fmaf(_v, _w0.y, acc[1]); \
    acc[2]  = fmaf(_v, _w0.z, acc[2]);  acc[3]  = fmaf(_v, _w0.w, acc[3]); \
    acc[4]  = fmaf(_v, _w1.x, acc[4]);  acc[5]  = fmaf(_v, _w1.y, acc[5]); \
    acc[6]  = fmaf(_v, _w1.z, acc[6]);  acc[7]  = fmaf(_v, _w1.w, acc[7]); \
    acc[8]  = fmaf(_v, _w2.x, acc[8]);  acc[9]  = fmaf(_v, _w2.y, acc[9]); \
    acc[10] = fmaf(_v, _w2.z, acc[10]); acc[11] = fmaf(_v, _w2.w, acc[11]);\
    acc[12] = fmaf(_v, _w3.x, acc[12]); acc[13] = fmaf(_v, _w3.y, acc[13]);\
    acc[14] = fmaf(_v, _w3.z, acc[14]);                                    \
} while (0)

__global__ void prep_kernel(const float* __restrict__ Wi, const float* __restrict__ mask) {
    int t = threadIdx.x;
    for (int idx = t; idx < 66 * 16; idx += 256) {
        int k = idx >> 4, u = idx & 15;
        g_WiT[idx] = (u < 15) ? Wi[u * 66 + k] : 0.0f;
    }
    for (int idx = t; idx < 256; idx += 256) g_reffT[idx] = 0.0f;
    if (t == 0) {
        int np = 0;
        for (int idx = 0; idx < 225; idx++) {
            if (mask[idx] != 0.0f) {
                g_pidx[np] = idx;
                g_pi[np] = idx / 15;
                g_pj[np] = idx % 15;
                np++;
            }
        }
        g_np = np;
    }
}

// Pack image window rows 6..21, cols 4..23 (float4-aligned both sides).
__global__ void prefetch_kernel(const float* __restrict__ x, int B) {
    int idx = blockIdx.x * 256 + threadIdx.x;
    if (idx >= B * 80) return;
    int b = idx / 80;
    int k = idx - b * 80;
    int row = k / 5;
    int c4 = k - row * 5;
    const float4* src = (const float4*)(x + (size_t)b * (IM * IM) + (6 + row) * IM + 4);
    float4* dst = (float4*)(g_win + (size_t)b * WIN_F + row * WROW);
    dst[c4] = src[c4];
}

// MODE 0: first step (no recurrent, emit coact). 1: middle. 2: last (logits).
template <int MODE>
__global__ __launch_bounds__(TPB, 8) void step_kernel(
    const float* __restrict__ bi, const float* __restrict__ gamma,
    const float* __restrict__ beta, const float* __restrict__ rb,
    const float* __restrict__ Wc, const float* __restrict__ bc,
    const float* __restrict__ Wo, const float* __restrict__ bo,
    float* __restrict__ out, int B)
{
    __shared__ __align__(16) float sh_wi[66 * 16];
    __shared__ __align__(16) float sh_rf[16 * 16];
    __shared__ float sh_s[BAG][TPB];
    __shared__ float sh_w[NPMAX][4];

    int tid = threadIdx.x;
    {
        const float4* s = (const float4*)g_WiT;
        float4* d = (float4*)sh_wi;
        for (int i = tid; i < 264; i += TPB) d[i] = s[i];
        if (MODE) {
            const float4* s2 = (const float4*)g_reffT;
            float4* d2 = (float4*)sh_rf;
            if (tid < 64) d2[tid] = s2[tid];
        }
    }
    __syncthreads();

    int b = blockIdx.x * TPB + tid;
    int bb = (b < B) ? b : 0;
    bool on = (b < B);

    int r, c;
    if (MODE == 0) { r = 10; c = 10; }
    else { unsigned int p = g_pos[bb]; r = (int)(p & 255u); c = (int)(p >> 8); }

    float acc[15];
#pragma unroll
    for (int u = 0; u < 15; u++) acc[u] = bi[u] + (MODE ? rb[u] : 0.0f);

    if (MODE) {
#pragma unroll
        for (int j = 0; j < 15; j++) {
            float so = g_state[j * MAXB + bb];
            FMA15S(so, sh_rf + j * 16);
        }
        float pr = (float)r * (2.0f / (float)POSMAX) - 1.0f;
        float pc = (float)c * (2.0f / (float)POSMAX) - 1.0f;
        FMA15S(pr, sh_wi + 64 * 16);
        FMA15S(pc, sh_wi + 65 * 16);
    }

    // ---- 8x8 patch from packed window (L2-resident) ----
    {
        int o = c - 4;            // in [2,10]
        int q = o & ~3;
        int sh = o & 3;
        const float* win = g_win + (size_t)bb * WIN_F + (r - 6) * WROW + q;
        bool s2 = (sh & 2) != 0;
        bool s1 = (sh & 1) != 0;
        bool need2 = (sh != 0);
#pragma unroll
        for (int i = 0; i < 8; i++) {
            const float4* rp = (const float4*)(win + i * WROW);
            float4 a0 = rp[0];
            float4 a1 = rp[1];
            float4 a2 = need2 ? rp[2] : make_float4(0.f, 0.f, 0.f, 0.f);
            float v0 = a0.x, v1 = a0.y, v2 = a0.z, v3 = a0.w;
            float v4 = a1.x, v5 = a1.y, v6 = a1.z, v7 = a1.w;
            float v8 = a2.x, v9 = a2.y, v10 = a2.z;
            float t0 = s2 ? v2 : v0, t1 = s2 ? v3 : v1, t2 = s2 ? v4 : v2;
            float t3 = s2 ? v5 : v3, t4 = s2 ? v6 : v4, t5 = s2 ? v7 : v5;
            float t6 = s2 ? v8 : v6, t7 = s2 ? v9 : v7, t8 = s2 ? v10 : v8;
            float f0 = s1 ? t1 : t0, f1 = s1 ? t2 : t1, f2 = s1 ? t3 : t2;
            float f3 = s1 ? t4 : t3, f4 = s1 ? t5 : t4, f5 = s1 ? t6 : t5;
            float f6 = s1 ? t7 : t6, f7 = s1 ? t8 : t7;
            FMA15S(f0, sh_wi + (i * 8 + 0) * 16);
            FMA15S(f1, sh_wi + (i * 8 + 1) * 16);
            FMA15S(f2, sh_wi + (i * 8 + 2) * 16);
            FMA15S(f3, sh_wi + (i * 8 + 3) * 16);
            FMA15S(f4, sh_wi + (i * 8 + 4) * 16);
            FMA15S(f5, sh_wi + (i * 8 + 5) * 16);
            FMA15S(f6, sh_wi + (i * 8 + 6) * 16);
            FMA15S(f7, sh_wi + (i * 8 + 7) * 16);
        }
    }

    // ---- relu + layernorm ----
    float mu = 0.0f;
#pragma unroll
    for (int u = 0; u < 15; u++) { acc[u] = fmaxf(acc[u], 0.0f); mu += acc[u]; }
    mu *= (1.0f / 15.0f);
    float var = 0.0f;
#pragma unroll
    for (int u = 0; u < 15; u++) { float d = acc[u] - mu; acc[u] = d; var += d * d; }
    var *= (1.0f / 15.0f);
    float inv = rsqrtf(var + 1e-5f);
    float s[15];
#pragma unroll
    for (int u = 0; u < 15; u++) s[u] = acc[u] * inv * gamma[u] + beta[u];

    if (MODE < 2) {
        if (on) {
#pragma unroll
            for (int u = 0; u < 15; u++) g_state[u * MAXB + b] = s[u];
        }
        // control head (tanh skipped: odd + strictly monotone, decisions identical)
        float c0 = bc[0], c1 = bc[1];
#pragma unroll
        for (int u = 0; u < 15; u++) {
            c0 = fmaf(s[u], Wc[u], c0);
            c1 = fmaf(s[u], Wc[15 + u], c1);
        }
        bool rsel = fabsf(c0) >= fabsf(c1);
        int mr = rsel ? ((c0 > 0.0f) ? 1 : ((c0 < 0.0f) ? -1 : 0)) : 0;
        int mc = rsel ? 0 : ((c1 > 0.0f) ? 1 : ((c1 < 0.0f) ? -1 : 0));
        int nr = min(max(r + mr, 0), POSMAX);
        int nc = min(max(c + mc, 0), POSMAX);
        if (on) g_pos[b] = (unsigned int)nr | ((unsigned int)nc << 8);

        // coact partials over active pairs only (deterministic order)
#pragma unroll
        for (int u = 0; u < 15; u++) sh_s[u][tid] = on ? s[u] : 0.0f;
        __syncthreads();
        int np = g_np;
        int wid = tid >> 5, lane = tid & 31;
        for (int p = 0; p < np; p++) {
            float v = sh_s[g_pi[p]][tid] * sh_s[g_pj[p]][tid];
            v = warp_sum(v);
            if (lane == 0) sh_w[p][wid] = v;
        }
        __syncthreads();
        for (int p = tid; p < np; p += TPB)
            g_partial[p * MAXBLK + blockIdx.x] =
                (sh_w[p][0] + sh_w[p][1]) + (sh_w[p][2] + sh_w[p][3]);
    } else {
        if (on) {
#pragma unroll
            for (int o2 = 0; o2 < 10; o2++) {
                float l = bo[o2];
#pragma unroll
                for (int u = 0; u < 15; u++) l = fmaf(s[u], Wo[o2 * 15 + u], l);
                out[(size_t)b * 10 + o2] = l;
            }
        }
    }
}

__global__ void reff_kernel(const float* __restrict__ R, const float* __restrict__ mask,
                            int B, int nblk) {
    int tid = threadIdx.x;
    // zero masked-out entries + padding (disjoint from active writes below)
    for (int idx = tid; idx < 240; idx += 256) {
        if (idx < 225) {
            int i = idx / 15, j = idx % 15;
            if (mask[idx] == 0.0f) g_reffT[j * 16 + i] = 0.0f;
        } else {
            g_reffT[(idx - 225) * 16 + 15] = 0.0f;
        }
    }
    int np = g_np;
    int wid = tid >> 5, lane = tid & 31;
    for (int p = wid; p < np; p += 8) {
        float a = 0.0f;
        for (int t = lane; t < nblk; t += 32) a += g_partial[p * MAXBLK + t];
        a = warp_sum(a);
        if (lane == 0) {
            int idx = g_pidx[p];
            int i = idx / 15, j = idx % 15;
            g_reffT[j * 16 + i] = (R[idx] - LAM * (a / (float)B)) * mask[idx];
        }
    }
}

extern "C" void kernel_launch(void* const* d_in, const int* in_sizes, int n_in,
                              void* d_out, int out_size) {
    const float* x     = (const float*)d_in[0];
    const float* Wi    = (const float*)d_in[1];
    const float* bi    = (const float*)d_in[2];
    const float* gamma = (const float*)d_in[3];
    const float* beta  = (const float*)d_in[4];
    const float* R     = (const float*)d_in[5];
    const float* rb    = (const float*)d_in[6];
    const float* mask  = (const float*)d_in[7];
    const float* Wc    = (const float*)d_in[8];
    const float* bc    = (const float*)d_in[9];
    const float* Wo    = (const float*)d_in[10];
    const float* bo    = (const float*)d_in[11];
    float* out = (float*)d_out;

    int B = in_sizes[0] / (IM * IM);
    if (B > MAXB) B = MAXB;
    int nblk = (B + TPB - 1) / TPB;
    int pblk = (B * 80 + 255) / 256;

    prep_kernel<<<1, 256>>>(Wi, mask);
    prefetch_kernel<<<pblk, 256>>>(x, B);
    step_kernel<0><<<nblk, TPB>>>(bi, gamma, beta, rb, Wc, bc, Wo, bo, out, B);
    reff_kernel<<<1, 256>>>(R, mask, B, nblk);
    step_kernel<1><<<nblk, TPB>>>(bi, gamma, beta, rb, Wc, bc, Wo, bo, out, B);
    reff_kernel<<<1, 256>>>(R, mask, B, nblk);
    step_kernel<1><<<nblk, TPB>>>(bi, gamma, beta, rb, Wc, bc, Wo, bo, out, B);
    reff_kernel<<<1, 256>>>(R, mask, B, nblk);
    step_kernel<1><<<nblk, TPB>>>(bi, gamma, beta, rb, Wc, bc, Wo, bo, out, B);
    reff_kernel<<<1, 256>>>(R, mask, B, nblk);
    step_kernel<2><<<nblk, TPB>>>(bi, gamma, beta, rb, Wc, bc, Wo, bo, out, B);
}

// round 11
// speedup vs baseline: 1.2860x; 1.2860x over previous
#include <cuda_runtime.h>

#define BAG 15
#define IM 28
#define POSMAX 20
#define LAM 0.001f
#define TPB 128
#define MAXB 65536
#define MAXBLK 512
#define NPMAX 225
#define WROW 20            /* packed window row: cols 4..23 of image */
#define WIN_F (16 * WROW)  /* 320 floats per sample */

__device__ __align__(16) float g_WiT[66 * 16];   // WiT[k*16+u] = Wi[u*66+k], col 15 = 0
__device__ __align__(16) float g_reffT[16 * 16]; // [j*16+u] = Reff[u][j]
__device__ float g_state[BAG * MAXB];            // [u][b]
__device__ unsigned int g_pos[MAXB];             // r | (c<<8)
__device__ float g_partial[NPMAX * MAXBLK];      // [pair][block]
__device__ int g_pidx[NPMAX];
__device__ int g_pi[NPMAX];
__device__ int g_pj[NPMAX];
__device__ int g_np;
__device__ __align__(16) float g_win[(size_t)MAXB * WIN_F]; // packed 16x20 windows (~84MB)

__device__ __forceinline__ float warp_sum(float v) {
    v += __shfl_xor_sync(0xffffffffu, v, 16);
    v += __shfl_xor_sync(0xffffffffu, v, 8);
    v += __shfl_xor_sync(0xffffffffu, v, 4);
    v += __shfl_xor_sync(0xffffffffu, v, 2);
    v += __shfl_xor_sync(0xffffffffu, v, 1);
    return v;
}

// acc[0..14] += val * base[0..14]   (base 16B-aligned shared, padded to 16 floats)
#define FMA15S(val, base) do {                                             \
    const float4* _wp = (const float4*)(base);                             \
    float4 _w0 = _wp[0], _w1 = _wp[1], _w2 = _wp[2], _w3 = _wp[3];         \
    float _v = (val);                                                      \
    acc[0]  = fmaf(_v, _w0.x, acc[0]);  acc[1]  = fmaf(_v, _w0.y, acc[1]); \
    acc[2]  = fmaf(_v, _w0.z, acc[2]);  acc[3]  = fmaf(_v, _w0.w, acc[3]); \
    acc[4]  = fmaf(_v, _w1.x, acc[4]);  acc[5]  = fmaf(_v, _w1.y, acc[5]); \
    acc[6]  = fmaf(_v, _w1.z, acc[6]);  acc[7]  = fmaf(_v, _w1.w, acc[7]); \
    acc[8]  = fmaf(_v, _w2.x, acc[8]);  acc[9]  = fmaf(_v, _w2.y, acc[9]); \
    acc[10] = fmaf(_v, _w2.z, acc[10]); acc[11] = fmaf(_v, _w2.w, acc[11]);\
    acc[12] = fmaf(_v, _w3.x, acc[12]); acc[13] = fmaf(_v, _w3.y, acc[13]);\
    acc[14] = fmaf(_v, _w3.z, acc[14]);                                    \
} while (0)

__global__ void prep_kernel(const float* __restrict__ Wi, const float* __restrict__ mask) {
    int t = threadIdx.x;
    for (int idx = t; idx < 66 * 16; idx += 256) {
        int k = idx >> 4, u = idx & 15;
        g_WiT[idx] = (u < 15) ? Wi[u * 66 + k] : 0.0f;
    }
    for (int idx = t; idx < 256; idx += 256) g_reffT[idx] = 0.0f;
    if (t == 0) {
        int np = 0;
        for (int idx = 0; idx < 225; idx++) {
            if (mask[idx] != 0.0f) {
                g_pidx[np] = idx;
                g_pi[np] = idx / 15;
                g_pj[np] = idx % 15;
                np++;
            }
        }
        g_np = np;
    }
}

// MODE 0: first step (fixed pos (10,10), packs window to g_win, emits coact).
// MODE 1: middle (recurrent, reads g_win, emits coact).
// MODE 2: last (recurrent, reads g_win, writes logits).
template <int MODE>
__global__ __launch_bounds__(TPB, 6) void step_kernel(
    const float* __restrict__ x,
    const float* __restrict__ bi, const float* __restrict__ gamma,
    const float* __restrict__ beta, const float* __restrict__ rb,
    const float* __restrict__ Wc, const float* __restrict__ bc,
    const float* __restrict__ Wo, const float* __restrict__ bo,
    float* __restrict__ out, int B)
{
    __shared__ __align__(16) float sh_wi[66 * 16];
    __shared__ __align__(16) float sh_rf[16 * 16];
    __shared__ float sh_s[BAG][TPB];
    __shared__ float sh_w[NPMAX][4];

    int tid = threadIdx.x;
    {
        const float4* s = (const float4*)g_WiT;
        float4* d = (float4*)sh_wi;
        for (int i = tid; i < 264; i += TPB) d[i] = s[i];
        if (MODE) {
            const float4* s2 = (const float4*)g_reffT;
            float4* d2 = (float4*)sh_rf;
            if (tid < 64) d2[tid] = s2[tid];
        }
    }
    __syncthreads();

    int b = blockIdx.x * TPB + tid;
    int bb = (b < B) ? b : 0;
    bool on = (b < B);

    int r, c;
    if (MODE == 0) { r = 10; c = 10; }
    else { unsigned int p = g_pos[bb]; r = (int)(p & 255u); c = (int)(p >> 8); }

    float acc[15];
#pragma unroll
    for (int u = 0; u < 15; u++) acc[u] = bi[u] + (MODE ? rb[u] : 0.0f);

    if (MODE) {
#pragma unroll
        for (int j = 0; j < 15; j++) {
            float so = g_state[j * MAXB + bb];
            FMA15S(so, sh_rf + j * 16);
        }
        float pr = (float)r * (2.0f / (float)POSMAX) - 1.0f;
        float pc = (float)c * (2.0f / (float)POSMAX) - 1.0f;
        FMA15S(pr, sh_wi + 64 * 16);
        FMA15S(pc, sh_wi + 65 * 16);
    }

    if (MODE == 0) {
        // Read full 16x20 window (rows 6..21, cols 4..23), pack into g_win,
        // and FMA the fixed center patch. Patch (10,10): rows = window rows
        // 4..11, cols = window floats 6..13 = w1.z .. w3.y.
        const float* img = x + (size_t)bb * (IM * IM);
        float* wout = g_win + (size_t)bb * WIN_F;
#pragma unroll
        for (int row = 0; row < 16; row++) {
            const float4* rp = (const float4*)(img + (6 + row) * IM + 4);
            float4 w0 = rp[0], w1 = rp[1], w2 = rp[2], w3 = rp[3], w4 = rp[4];
            if (on) {
                float4* wp = (float4*)(wout + row * WROW);
                wp[0] = w0; wp[1] = w1; wp[2] = w2; wp[3] = w3; wp[4] = w4;
            }
            if (row >= 4 && row <= 11) {
                int i = row - 4;
                FMA15S(w1.z, sh_wi + (i * 8 + 0) * 16);
                FMA15S(w1.w, sh_wi + (i * 8 + 1) * 16);
                FMA15S(w2.x, sh_wi + (i * 8 + 2) * 16);
                FMA15S(w2.y, sh_wi + (i * 8 + 3) * 16);
                FMA15S(w2.z, sh_wi + (i * 8 + 4) * 16);
                FMA15S(w2.w, sh_wi + (i * 8 + 5) * 16);
                FMA15S(w3.x, sh_wi + (i * 8 + 6) * 16);
                FMA15S(w3.y, sh_wi + (i * 8 + 7) * 16);
            }
        }
    } else {
        // 8x8 patch from packed window (L2-resident)
        int o = c - 4;            // in [2,10]
        int q = o & ~3;
        int sh = o & 3;
        const float* win = g_win + (size_t)bb * WIN_F + (r - 6) * WROW + q;
        bool s2 = (sh & 2) != 0;
        bool s1 = (sh & 1) != 0;
        bool need2 = (sh != 0);
#pragma unroll
        for (int i = 0; i < 8; i++) {
            const float4* rp = (const float4*)(win + i * WROW);
            float4 a0 = rp[0];
            float4 a1 = rp[1];
            float4 a2 = need2 ? rp[2] : make_float4(0.f, 0.f, 0.f, 0.f);
            float v0 = a0.x, v1 = a0.y, v2 = a0.z, v3 = a0.w;
            float v4 = a1.x, v5 = a1.y, v6 = a1.z, v7 = a1.w;
            float v8 = a2.x, v9 = a2.y, v10 = a2.z;
            float t0 = s2 ? v2 : v0, t1 = s2 ? v3 : v1, t2 = s2 ? v4 : v2;
            float t3 = s2 ? v5 : v3, t4 = s2 ? v6 : v4, t5 = s2 ? v7 : v5;
            float t6 = s2 ? v8 : v6, t7 = s2 ? v9 : v7, t8 = s2 ? v10 : v8;
            float f0 = s1 ? t1 : t0, f1 = s1 ? t2 : t1, f2 = s1 ? t3 : t2;
            float f3 = s1 ? t4 : t3, f4 = s1 ? t5 : t4, f5 = s1 ? t6 : t5;
            float f6 = s1 ? t7 : t6, f7 = s1 ? t8 : t7;
            FMA15S(f0, sh_wi + (i * 8 + 0) * 16);
            FMA15S(f1, sh_wi + (i * 8 + 1) * 16);
            FMA15S(f2, sh_wi + (i * 8 + 2) * 16);
            FMA15S(f3, sh_wi + (i * 8 + 3) * 16);
            FMA15S(f4, sh_wi + (i * 8 + 4) * 16);
            FMA15S(f5, sh_wi + (i * 8 + 5) * 16);
            FMA15S(f6, sh_wi + (i * 8 + 6) * 16);
            FMA15S(f7, sh_wi + (i * 8 + 7) * 16);
        }
    }

    // ---- relu + layernorm ----
    float mu = 0.0f;
#pragma unroll
    for (int u = 0; u < 15; u++) { acc[u] = fmaxf(acc[u], 0.0f); mu += acc[u]; }
    mu *= (1.0f / 15.0f);
    float var = 0.0f;
#pragma unroll
    for (int u = 0; u < 15; u++) { float d = acc[u] - mu; acc[u] = d; var += d * d; }
    var *= (1.0f / 15.0f);
    float inv = rsqrtf(var + 1e-5f);
    float s[15];
#pragma unroll
    for (int u = 0; u < 15; u++) s[u] = acc[u] * inv * gamma[u] + beta[u];

    if (MODE < 2) {
        if (on) {
#pragma unroll
            for (int u = 0; u < 15; u++) g_state[u * MAXB + b] = s[u];
        }
        // control head (tanh skipped: odd + strictly monotone, decisions identical)
        float c0 = bc[0], c1 = bc[1];
#pragma unroll
        for (int u = 0; u < 15; u++) {
            c0 = fmaf(s[u], Wc[u], c0);
            c1 = fmaf(s[u], Wc[15 + u], c1);
        }
        bool rsel = fabsf(c0) >= fabsf(c1);
        int mr = rsel ? ((c0 > 0.0f) ? 1 : ((c0 < 0.0f) ? -1 : 0)) : 0;
        int mc = rsel ? 0 : ((c1 > 0.0f) ? 1 : ((c1 < 0.0f) ? -1 : 0));
        int nr = min(max(r + mr, 0), POSMAX);
        int nc = min(max(c + mc, 0), POSMAX);
        if (on) g_pos[b] = (unsigned int)nr | ((unsigned int)nc << 8);

        // coact partials over active pairs only (deterministic order)
#pragma unroll
        for (int u = 0; u < 15; u++) sh_s[u][tid] = on ? s[u] : 0.0f;
        __syncthreads();
        int np = g_np;
        int wid = tid >> 5, lane = tid & 31;
        for (int p = 0; p < np; p++) {
            float v = sh_s[g_pi[p]][tid] * sh_s[g_pj[p]][tid];
            v = warp_sum(v);
            if (lane == 0) sh_w[p][wid] = v;
        }
        __syncthreads();
        for (int p = tid; p < np; p += TPB)
            g_partial[p * MAXBLK + blockIdx.x] =
                (sh_w[p][0] + sh_w[p][1]) + (sh_w[p][2] + sh_w[p][3]);
    } else {
        if (on) {
#pragma unroll
            for (int o2 = 0; o2 < 10; o2++) {
                float l = bo[o2];
#pragma unroll
                for (int u = 0; u < 15; u++) l = fmaf(s[u], Wo[o2 * 15 + u], l);
                out[(size_t)b * 10 + o2] = l;
            }
        }
    }
}

// 1024 threads: one warp per active pair, float4 loads, MLP=4, fully unrolled.
__global__ void reff_kernel(const float* __restrict__ R, const float* __restrict__ mask,
                            int B, int nblk) {
    int tid = threadIdx.x;
    int wid = tid >> 5, lane = tid & 31;
    int np = g_np;
    for (int p = wid; p < np; p += 32) {
        float a;
        if (nblk == MAXBLK) {
            const float4* pp = (const float4*)(g_partial + p * MAXBLK);
            float4 a0 = pp[lane];
            float4 a1 = pp[32 + lane];
            float4 a2 = pp[64 + lane];
            float4 a3 = pp[96 + lane];
            a = ((a0.x + a0.y) + (a0.z + a0.w)) + ((a1.x + a1.y) + (a1.z + a1.w))
              + ((a2.x + a2.y) + (a2.z + a2.w)) + ((a3.x + a3.y) + (a3.z + a3.w));
        } else {
            a = 0.0f;
            for (int t = lane; t < nblk; t += 32) a += g_partial[p * MAXBLK + t];
        }
        a = warp_sum(a);
        if (lane == 0) {
            int idx = g_pidx[p];
            int i = idx / 15, j = idx % 15;
            g_reffT[j * 16 + i] = (R[idx] - LAM * (a / (float)B)) * mask[idx];
        }
    }
}

extern "C" void kernel_launch(void* const* d_in, const int* in_sizes, int n_in,
                              void* d_out, int out_size) {
    const float* x     = (const float*)d_in[0];
    const float* Wi    = (const float*)d_in[1];
    const float* bi    = (const float*)d_in[2];
    const float* gamma = (const float*)d_in[3];
    const float* beta  = (const float*)d_in[4];
    const float* R     = (const float*)d_in[5];
    const float* rb    = (const float*)d_in[6];
    const float* mask  = (const float*)d_in[7];
    const float* Wc    = (const float*)d_in[8];
    const float* bc    = (const float*)d_in[9];
    const float* Wo    = (const float*)d_in[10];
    const float* bo    = (const float*)d_in[11];
    float* out = (float*)d_out;

    int B = in_sizes[0] / (IM * IM);
    if (B > MAXB) B = MAXB;
    int nblk = (B + TPB - 1) / TPB;

    prep_kernel<<<1, 256>>>(Wi, mask);
    step_kernel<0><<<nblk, TPB>>>(x, bi, gamma, beta, rb, Wc, bc, Wo, bo, out, B);
    reff_kernel<<<1, 1024>>>(R, mask, B, nblk);
    step_kernel<1><<<nblk, TPB>>>(x, bi, gamma, beta, rb, Wc, bc, Wo, bo, out, B);
    reff_kernel<<<1, 1024>>>(R, mask, B, nblk);
    step_kernel<1><<<nblk, TPB>>>(x, bi, gamma, beta, rb, Wc, bc, Wo, bo, out, B);
    reff_kernel<<<1, 1024>>>(R, mask, B, nblk);
    step_kernel<1><<<nblk, TPB>>>(x, bi, gamma, beta, rb, Wc, bc, Wo, bo, out, B);
    reff_kernel<<<1, 1024>>>(R, mask, B, nblk);
    step_kernel<2><<<nblk, TPB>>>(x, bi, gamma, beta, rb, Wc, bc, Wo, bo, out, B);
}

// round 12
// speedup vs baseline: 1.4649x; 1.1391x over previous
#include <cuda_runtime.h>

#define BAG 15
#define IM 28
#define POSMAX 20
#define LAM 0.001f
#define TPB 128
#define MAXB 65536
#define NPMAX 225
#define WROW 20            /* packed window row: cols 4..23 of image */
#define WIN_F (16 * WROW)  /* 320 floats per sample */

__device__ __align__(16) float g_WiT[66 * 16];   // WiT[k*16+u] = Wi[u*66+k], col 15 = 0
__device__ __align__(16) float g_reffT[16 * 16]; // [j*16+u] = Reff[u][j]
__device__ float g_state[BAG * MAXB];            // [u][b]
__device__ unsigned int g_pos[MAXB];             // r | (c<<8)
__device__ float g_partial[(size_t)NPMAX * MAXB];// [pair][b] lane products
__device__ int g_pidx[NPMAX];                    // flattened mask index of active pairs
__device__ int g_pij[NPMAX];                     // i | (j<<8)
__device__ int g_np;
__device__ __align__(16) float g_win[(size_t)MAXB * WIN_F]; // packed 16x20 windows (~84MB)

__device__ __forceinline__ float warp_sum(float v) {
    v += __shfl_xor_sync(0xffffffffu, v, 16);
    v += __shfl_xor_sync(0xffffffffu, v, 8);
    v += __shfl_xor_sync(0xffffffffu, v, 4);
    v += __shfl_xor_sync(0xffffffffu, v, 2);
    v += __shfl_xor_sync(0xffffffffu, v, 1);
    return v;
}

// acc[0..14] += val * base[0..14]   (base 16B-aligned shared, padded to 16 floats)
#define FMA15S(val, base) do {                                             \
    const float4* _wp = (const float4*)(base);                             \
    float4 _w0 = _wp[0], _w1 = _wp[1], _w2 = _wp[2], _w3 = _wp[3];         \
    float _v = (val);                                                      \
    acc[0]  = fmaf(_v, _w0.x, acc[0]);  acc[1]  = fmaf(_v, _w0.y, acc[1]); \
    acc[2]  = fmaf(_v, _w0.z, acc[2]);  acc[3]  = fmaf(_v, _w0.w, acc[3]); \
    acc[4]  = fmaf(_v, _w1.x, acc[4]);  acc[5]  = fmaf(_v, _w1.y, acc[5]); \
    acc[6]  = fmaf(_v, _w1.z, acc[6]);  acc[7]  = fmaf(_v, _w1.w, acc[7]); \
    acc[8]  = fmaf(_v, _w2.x, acc[8]);  acc[9]  = fmaf(_v, _w2.y, acc[9]); \
    acc[10] = fmaf(_v, _w2.z, acc[10]); acc[11] = fmaf(_v, _w2.w, acc[11]);\
    acc[12] = fmaf(_v, _w3.x, acc[12]); acc[13] = fmaf(_v, _w3.y, acc[13]);\
    acc[14] = fmaf(_v, _w3.z, acc[14]);                                    \
} while (0)

__global__ void prep_kernel(const float* __restrict__ Wi, const float* __restrict__ mask) {
    int t = threadIdx.x;
    for (int idx = t; idx < 66 * 16; idx += 256) {
        int k = idx >> 4, u = idx & 15;
        g_WiT[idx] = (u < 15) ? Wi[u * 66 + k] : 0.0f;
    }
    for (int idx = t; idx < 256; idx += 256) g_reffT[idx] = 0.0f;
    if (t == 0) {
        int np = 0;
        for (int idx = 0; idx < 225; idx++) {
            if (mask[idx] != 0.0f) {
                g_pidx[np] = idx;
                g_pij[np] = (idx / 15) | ((idx % 15) << 8);
                np++;
            }
        }
        g_np = np;
    }
}

// Coalesced window pack (verified in R8): rows 6..21, cols 4..23 -> g_win.
// __ldcs streams x through L2 so the packed window stays resident.
__global__ void pack_kernel(const float* __restrict__ x, int B) {
    int idx = blockIdx.x * 256 + threadIdx.x;
    if (idx >= B * 80) return;
    int b = idx / 80;
    int k = idx - b * 80;
    int row = k / 5;
    int c4 = k - row * 5;
    const float4* src = (const float4*)(x + (size_t)b * (IM * IM) + (6 + row) * IM + 4);
    float4* dst = (float4*)(g_win + (size_t)b * WIN_F + row * WROW);
    dst[c4] = __ldcs(&src[c4]);
}

// MODE 0: first step (fixed pos (10,10), no recurrent, lane products).
// MODE 1: middle (recurrent, lane products). MODE 2: last (recurrent, logits).
template <int MODE>
__global__ __launch_bounds__(TPB, 6) void step_kernel(
    const float* __restrict__ bi, const float* __restrict__ gamma,
    const float* __restrict__ beta, const float* __restrict__ rb,
    const float* __restrict__ Wc, const float* __restrict__ bc,
    const float* __restrict__ Wo, const float* __restrict__ bo,
    float* __restrict__ out, int B)
{
    __shared__ __align__(16) float sh_wi[66 * 16];
    __shared__ __align__(16) float sh_rf[16 * 16];
    __shared__ float sh_s[BAG][TPB];
    __shared__ int sh_pp[NPMAX];

    int tid = threadIdx.x;
    int b = blockIdx.x * TPB + tid;
    int bb = (b < B) ? b : 0;
    bool on = (b < B);

    // issue position + state loads first (one overlapped latency window)
    int r, c;
    if (MODE == 0) { r = 10; c = 10; }
    else { unsigned int p = g_pos[bb]; r = (int)(p & 255u); c = (int)(p >> 8); }
    float st[15];
    if (MODE) {
#pragma unroll
        for (int j = 0; j < 15; j++) st[j] = g_state[j * MAXB + bb];
    }

    // stage weights (and pair list) into shared
    {
        const float4* s = (const float4*)g_WiT;
        float4* d = (float4*)sh_wi;
        for (int i = tid; i < 264; i += TPB) d[i] = s[i];
        if (MODE) {
            const float4* s2 = (const float4*)g_reffT;
            float4* d2 = (float4*)sh_rf;
            if (tid < 64) d2[tid] = s2[tid];
        }
        if (MODE < 2)
            for (int i = tid; i < NPMAX; i += TPB) sh_pp[i] = g_pij[i];
    }
    __syncthreads();

    float acc[15];
#pragma unroll
    for (int u = 0; u < 15; u++) acc[u] = bi[u] + (MODE ? rb[u] : 0.0f);

    if (MODE) {
#pragma unroll
        for (int j = 0; j < 15; j++) FMA15S(st[j], sh_rf + j * 16);
        float pr = (float)r * (2.0f / (float)POSMAX) - 1.0f;
        float pc = (float)c * (2.0f / (float)POSMAX) - 1.0f;
        FMA15S(pr, sh_wi + 64 * 16);
        FMA15S(pc, sh_wi + 65 * 16);
    } else {
        float pm = 10.0f * (2.0f / (float)POSMAX) - 1.0f;  // = 0
        FMA15S(pm, sh_wi + 64 * 16);
        FMA15S(pm, sh_wi + 65 * 16);
    }

    // ---- 8x8 patch from packed window (L2-resident); verified R11 math ----
    {
        int o = c - 4;            // in [2,10]
        int q = o & ~3;
        int sh = o & 3;
        const float* win = g_win + (size_t)bb * WIN_F + (r - 6) * WROW + q;
        bool s2 = (sh & 2) != 0;
        bool s1 = (sh & 1) != 0;
        bool need2 = (sh != 0);
#pragma unroll
        for (int i = 0; i < 8; i++) {
            const float4* rp = (const float4*)(win + i * WROW);
            float4 a0 = rp[0];
            float4 a1 = rp[1];
            float4 a2 = need2 ? rp[2] : make_float4(0.f, 0.f, 0.f, 0.f);
            float v0 = a0.x, v1 = a0.y, v2 = a0.z, v3 = a0.w;
            float v4 = a1.x, v5 = a1.y, v6 = a1.z, v7 = a1.w;
            float v8 = a2.x, v9 = a2.y, v10 = a2.z;
            float t0 = s2 ? v2 : v0, t1 = s2 ? v3 : v1, t2 = s2 ? v4 : v2;
            float t3 = s2 ? v5 : v3, t4 = s2 ? v6 : v4, t5 = s2 ? v7 : v5;
            float t6 = s2 ? v8 : v6, t7 = s2 ? v9 : v7, t8 = s2 ? v10 : v8;
            float f0 = s1 ? t1 : t0, f1 = s1 ? t2 : t1, f2 = s1 ? t3 : t2;
            float f3 = s1 ? t4 : t3, f4 = s1 ? t5 : t4, f5 = s1 ? t6 : t5;
            float f6 = s1 ? t7 : t6, f7 = s1 ? t8 : t7;
            FMA15S(f0, sh_wi + (i * 8 + 0) * 16);
            FMA15S(f1, sh_wi + (i * 8 + 1) * 16);
            FMA15S(f2, sh_wi + (i * 8 + 2) * 16);
            FMA15S(f3, sh_wi + (i * 8 + 3) * 16);
            FMA15S(f4, sh_wi + (i * 8 + 4) * 16);
            FMA15S(f5, sh_wi + (i * 8 + 5) * 16);
            FMA15S(f6, sh_wi + (i * 8 + 6) * 16);
            FMA15S(f7, sh_wi + (i * 8 + 7) * 16);
        }
    }

    // ---- relu + layernorm ----
    float mu = 0.0f;
#pragma unroll
    for (int u = 0; u < 15; u++) { acc[u] = fmaxf(acc[u], 0.0f); mu += acc[u]; }
    mu *= (1.0f / 15.0f);
    float var = 0.0f;
#pragma unroll
    for (int u = 0; u < 15; u++) { float d = acc[u] - mu; acc[u] = d; var += d * d; }
    var *= (1.0f / 15.0f);
    float inv = rsqrtf(var + 1e-5f);
    float s[15];
#pragma unroll
    for (int u = 0; u < 15; u++) s[u] = acc[u] * inv * gamma[u] + beta[u];

    if (MODE < 2) {
        if (on) {
#pragma unroll
            for (int u = 0; u < 15; u++) g_state[u * MAXB + b] = s[u];
        }
        // control head (tanh skipped: odd + strictly monotone, decisions identical)
        float c0 = bc[0], c1 = bc[1];
#pragma unroll
        for (int u = 0; u < 15; u++) {
            c0 = fmaf(s[u], Wc[u], c0);
            c1 = fmaf(s[u], Wc[15 + u], c1);
        }
        bool rsel = fabsf(c0) >= fabsf(c1);
        int mr = rsel ? ((c0 > 0.0f) ? 1 : ((c0 < 0.0f) ? -1 : 0)) : 0;
        int mc = rsel ? 0 : ((c1 > 0.0f) ? 1 : ((c1 < 0.0f) ? -1 : 0));
        int nr = min(max(r + mr, 0), POSMAX);
        int nc = min(max(c + mc, 0), POSMAX);
        if (on) g_pos[b] = (unsigned int)nr | ((unsigned int)nc << 8);

        // lane products for coact: no syncs, no shuffles; reduce in reff_kernel.
        // sh_s only legalizes dynamic indexing; each thread reads its own column.
#pragma unroll
        for (int u = 0; u < 15; u++) sh_s[u][tid] = s[u];
        int np = g_np;
        if (on) {
            for (int p = 0; p < np; p++) {
                int e = sh_pp[p];
                int i = e & 255, j = e >> 8;
                float v = sh_s[i][tid] * sh_s[j][tid];
                __stcs(&g_partial[(size_t)p * MAXB + b], v);
            }
        }
    } else {
        if (on) {
#pragma unroll
            for (int o2 = 0; o2 < 10; o2++) {
                float l = bo[o2];
#pragma unroll
                for (int u = 0; u < 15; u++) l = fmaf(s[u], Wo[o2 * 15 + u], l);
                __stcs(&out[(size_t)b * 10 + o2], l);
            }
        }
    }
}

// One block per active pair; deterministic fixed-tree reduce over B products.
__global__ void reff_kernel(const float* __restrict__ R, const float* __restrict__ mask,
                            int B) {
    int p = blockIdx.x;
    if (p >= g_np) return;
    __shared__ float sh[8];
    const float4* s4 = (const float4*)(g_partial + (size_t)p * MAXB);
    int n4 = B >> 2;
    float a = 0.0f;
#pragma unroll 4
    for (int t = threadIdx.x; t < n4; t += 256) {
        float4 v = __ldcs(&s4[t]);
        a += (v.x + v.y) + (v.z + v.w);
    }
    a = warp_sum(a);
    if ((threadIdx.x & 31) == 0) sh[threadIdx.x >> 5] = a;
    __syncthreads();
    if (threadIdx.x == 0) {
        float t = ((sh[0] + sh[1]) + (sh[2] + sh[3])) + ((sh[4] + sh[5]) + (sh[6] + sh[7]));
        int idx = g_pidx[p];
        int i = idx / 15, j = idx % 15;
        g_reffT[j * 16 + i] = (R[idx] - LAM * (t / (float)B)) * mask[idx];
    }
}

extern "C" void kernel_launch(void* const* d_in, const int* in_sizes, int n_in,
                              void* d_out, int out_size) {
    const float* x     = (const float*)d_in[0];
    const float* Wi    = (const float*)d_in[1];
    const float* bi    = (const float*)d_in[2];
    const float* gamma = (const float*)d_in[3];
    const float* beta  = (const float*)d_in[4];
    const float* R     = (const float*)d_in[5];
    const float* rb    = (const float*)d_in[6];
    const float* mask  = (const float*)d_in[7];
    const float* Wc    = (const float*)d_in[8];
    const float* bc    = (const float*)d_in[9];
    const float* Wo    = (const float*)d_in[10];
    const float* bo    = (const float*)d_in[11];
    float* out = (float*)d_out;

    int B = in_sizes[0] / (IM * IM);
    if (B > MAXB) B = MAXB;
    int nblk = (B + TPB - 1) / TPB;
    int pblk = (B * 80 + 255) / 256;

    prep_kernel<<<1, 256>>>(Wi, mask);
    pack_kernel<<<pblk, 256>>>(x, B);
    step_kernel<0><<<nblk, TPB>>>(bi, gamma, beta, rb, Wc, bc, Wo, bo, out, B);
    reff_kernel<<<NPMAX, 256>>>(R, mask, B);
    step_kernel<1><<<nblk, TPB>>>(bi, gamma, beta, rb, Wc, bc, Wo, bo, out, B);
    reff_kernel<<<NPMAX, 256>>>(R, mask, B);
    step_kernel<1><<<nblk, TPB>>>(bi, gamma, beta, rb, Wc, bc, Wo, bo, out, B);
    reff_kernel<<<NPMAX, 256>>>(R, mask, B);
    step_kernel<1><<<nblk, TPB>>>(bi, gamma, beta, rb, Wc, bc, Wo, bo, out, B);
    reff_kernel<<<NPMAX, 256>>>(R, mask, B);
    step_kernel<2><<<nblk, TPB>>>(bi, gamma, beta, rb, Wc, bc, Wo, bo, out, B);
}

// round 13
// speedup vs baseline: 1.6534x; 1.1287x over previous
#include <cuda_runtime.h>

#define BAG 15
#define IM 28
#define POSMAX 20
#define LAM 0.001f
#define TPB 128
#define MAXB 65536
#define MAXW (MAXB / 32)   /* 2048 warps max */
#define NPMAX 225
#define WROW 20            /* packed window row: cols 4..23 of image */
#define WIN_F (16 * WROW)  /* 320 floats per sample */

__device__ __align__(16) float g_WiT[66 * 16];   // WiT[k*16+u] = Wi[u*66+k], col 15 = 0
__device__ __align__(16) float g_reffT[16 * 16]; // [j*16+u] = Reff[u][j]
__device__ float g_state[BAG * MAXB];            // [u][b]
__device__ unsigned int g_pos[MAXB];             // r | (c<<8)
__device__ float g_partial[NPMAX * MAXW];        // [pair][warp] partial sums (1.8MB)
__device__ int g_pidx[NPMAX];                    // flattened mask index of active pairs
__device__ int g_pij[NPMAX];                     // i | (j<<8)
__device__ int g_np;
__device__ __align__(16) float g_win[(size_t)MAXB * WIN_F]; // packed 16x20 windows (~84MB)

__device__ __forceinline__ float warp_sum(float v) {
    v += __shfl_xor_sync(0xffffffffu, v, 16);
    v += __shfl_xor_sync(0xffffffffu, v, 8);
    v += __shfl_xor_sync(0xffffffffu, v, 4);
    v += __shfl_xor_sync(0xffffffffu, v, 2);
    v += __shfl_xor_sync(0xffffffffu, v, 1);
    return v;
}

// acc[0..14] += val * base[0..14]   (base 16B-aligned shared, padded to 16 floats)
#define FMA15S(val, base) do {                                             \
    const float4* _wp = (const float4*)(base);                             \
    float4 _w0 = _wp[0], _w1 = _wp[1], _w2 = _wp[2], _w3 = _wp[3];         \
    float _v = (val);                                                      \
    acc[0]  = fmaf(_v, _w0.x, acc[0]);  acc[1]  = fmaf(_v, _w0.y, acc[1]); \
    acc[2]  = fmaf(_v, _w0.z, acc[2]);  acc[3]  = fmaf(_v, _w0.w, acc[3]); \
    acc[4]  = fmaf(_v, _w1.x, acc[4]);  acc[5]  = fmaf(_v, _w1.y, acc[5]); \
    acc[6]  = fmaf(_v, _w1.z, acc[6]);  acc[7]  = fmaf(_v, _w1.w, acc[7]); \
    acc[8]  = fmaf(_v, _w2.x, acc[8]);  acc[9]  = fmaf(_v, _w2.y, acc[9]); \
    acc[10] = fmaf(_v, _w2.z, acc[10]); acc[11] = fmaf(_v, _w2.w, acc[11]);\
    acc[12] = fmaf(_v, _w3.x, acc[12]); acc[13] = fmaf(_v, _w3.y, acc[13]);\
    acc[14] = fmaf(_v, _w3.z, acc[14]);                                    \
} while (0)

__global__ void prep_kernel(const float* __restrict__ Wi, const float* __restrict__ mask) {
    int t = threadIdx.x;
    for (int idx = t; idx < 66 * 16; idx += 256) {
        int k = idx >> 4, u = idx & 15;
        g_WiT[idx] = (u < 15) ? Wi[u * 66 + k] : 0.0f;
    }
    for (int idx = t; idx < 256; idx += 256) g_reffT[idx] = 0.0f;
    if (t == 0) {
        int np = 0;
        for (int idx = 0; idx < 225; idx++) {
            if (mask[idx] != 0.0f) {
                g_pidx[np] = idx;
                g_pij[np] = (idx / 15) | ((idx % 15) << 8);
                np++;
            }
        }
        g_np = np;
    }
}

// Coalesced window pack (verified): rows 6..21, cols 4..23 -> g_win.
// __ldcs streams x through L2 so the packed window stays resident.
__global__ void pack_kernel(const float* __restrict__ x, int B) {
    int idx = blockIdx.x * 256 + threadIdx.x;
    if (idx >= B * 80) return;
    int b = idx / 80;
    int k = idx - b * 80;
    int row = k / 5;
    int c4 = k - row * 5;
    const float4* src = (const float4*)(x + (size_t)b * (IM * IM) + (6 + row) * IM + 4);
    float4* dst = (float4*)(g_win + (size_t)b * WIN_F + row * WROW);
    dst[c4] = __ldcs(&src[c4]);
}

// MODE 0: first step (fixed pos (10,10), no recurrent, coact partials).
// MODE 1: middle (recurrent, coact partials). MODE 2: last (recurrent, logits).
template <int MODE>
__global__ __launch_bounds__(TPB, 6) void step_kernel(
    const float* __restrict__ bi, const float* __restrict__ gamma,
    const float* __restrict__ beta, const float* __restrict__ rb,
    const float* __restrict__ Wc, const float* __restrict__ bc,
    const float* __restrict__ Wo, const float* __restrict__ bo,
    float* __restrict__ out, int B, int NW)
{
    __shared__ __align__(16) float sh_wi[66 * 16];
    __shared__ __align__(16) float sh_rf[16 * 16];
    __shared__ float sh_s[BAG][TPB];
    __shared__ int sh_pp[NPMAX];

    int tid = threadIdx.x;
    int b = blockIdx.x * TPB + tid;
    int bb = (b < B) ? b : 0;
    bool on = (b < B);

    // issue position + state loads first (one overlapped latency window)
    int r, c;
    if (MODE == 0) { r = 10; c = 10; }
    else { unsigned int p = g_pos[bb]; r = (int)(p & 255u); c = (int)(p >> 8); }
    float st[15];
    if (MODE) {
#pragma unroll
        for (int j = 0; j < 15; j++) st[j] = g_state[j * MAXB + bb];
    }

    // stage weights (and pair list) into shared
    {
        const float4* s = (const float4*)g_WiT;
        float4* d = (float4*)sh_wi;
        for (int i = tid; i < 264; i += TPB) d[i] = s[i];
        if (MODE) {
            const float4* s2 = (const float4*)g_reffT;
            float4* d2 = (float4*)sh_rf;
            if (tid < 64) d2[tid] = s2[tid];
        }
        if (MODE < 2)
            for (int i = tid; i < NPMAX; i += TPB) sh_pp[i] = g_pij[i];
    }
    __syncthreads();

    float acc[15];
#pragma unroll
    for (int u = 0; u < 15; u++) acc[u] = bi[u] + (MODE ? rb[u] : 0.0f);

    if (MODE) {
#pragma unroll
        for (int j = 0; j < 15; j++) FMA15S(st[j], sh_rf + j * 16);
        float pr = (float)r * (2.0f / (float)POSMAX) - 1.0f;
        float pc = (float)c * (2.0f / (float)POSMAX) - 1.0f;
        FMA15S(pr, sh_wi + 64 * 16);
        FMA15S(pc, sh_wi + 65 * 16);
    } else {
        float pm = 0.0f;   // 10/20*2-1 = 0 for both coords
        FMA15S(pm, sh_wi + 64 * 16);
        FMA15S(pm, sh_wi + 65 * 16);
    }

    // ---- 8x8 patch from packed window (L2-resident); verified math ----
    {
        int o = c - 4;            // in [2,10]
        int q = o & ~3;
        int sh = o & 3;
        const float* win = g_win + (size_t)bb * WIN_F + (r - 6) * WROW + q;
        bool s2 = (sh & 2) != 0;
        bool s1 = (sh & 1) != 0;
        bool need2 = (sh != 0);
#pragma unroll
        for (int i = 0; i < 8; i++) {
            const float4* rp = (const float4*)(win + i * WROW);
            float4 a0 = rp[0];
            float4 a1 = rp[1];
            float4 a2 = need2 ? rp[2] : make_float4(0.f, 0.f, 0.f, 0.f);
            float v0 = a0.x, v1 = a0.y, v2 = a0.z, v3 = a0.w;
            float v4 = a1.x, v5 = a1.y, v6 = a1.z, v7 = a1.w;
            float v8 = a2.x, v9 = a2.y, v10 = a2.z;
            float t0 = s2 ? v2 : v0, t1 = s2 ? v3 : v1, t2 = s2 ? v4 : v2;
            float t3 = s2 ? v5 : v3, t4 = s2 ? v6 : v4, t5 = s2 ? v7 : v5;
            float t6 = s2 ? v8 : v6, t7 = s2 ? v9 : v7, t8 = s2 ? v10 : v8;
            float f0 = s1 ? t1 : t0, f1 = s1 ? t2 : t1, f2 = s1 ? t3 : t2;
            float f3 = s1 ? t4 : t3, f4 = s1 ? t5 : t4, f5 = s1 ? t6 : t5;
            float f6 = s1 ? t7 : t6, f7 = s1 ? t8 : t7;
            FMA15S(f0, sh_wi + (i * 8 + 0) * 16);
            FMA15S(f1, sh_wi + (i * 8 + 1) * 16);
            FMA15S(f2, sh_wi + (i * 8 + 2) * 16);
            FMA15S(f3, sh_wi + (i * 8 + 3) * 16);
            FMA15S(f4, sh_wi + (i * 8 + 4) * 16);
            FMA15S(f5, sh_wi + (i * 8 + 5) * 16);
            FMA15S(f6, sh_wi + (i * 8 + 6) * 16);
            FMA15S(f7, sh_wi + (i * 8 + 7) * 16);
        }
    }

    // ---- relu + layernorm ----
    float mu = 0.0f;
#pragma unroll
    for (int u = 0; u < 15; u++) { acc[u] = fmaxf(acc[u], 0.0f); mu += acc[u]; }
    mu *= (1.0f / 15.0f);
    float var = 0.0f;
#pragma unroll
    for (int u = 0; u < 15; u++) { float d = acc[u] - mu; acc[u] = d; var += d * d; }
    var *= (1.0f / 15.0f);
    float inv = rsqrtf(var + 1e-5f);
    float s[15];
#pragma unroll
    for (int u = 0; u < 15; u++) s[u] = acc[u] * inv * gamma[u] + beta[u];

    if (MODE < 2) {
        if (on) {
#pragma unroll
            for (int u = 0; u < 15; u++) g_state[u * MAXB + b] = s[u];
        }
        // control head (tanh skipped: odd + strictly monotone, decisions identical)
        float c0 = bc[0], c1 = bc[1];
#pragma unroll
        for (int u = 0; u < 15; u++) {
            c0 = fmaf(s[u], Wc[u], c0);
            c1 = fmaf(s[u], Wc[15 + u], c1);
        }
        bool rsel = fabsf(c0) >= fabsf(c1);
        int mr = rsel ? ((c0 > 0.0f) ? 1 : ((c0 < 0.0f) ? -1 : 0)) : 0;
        int mc = rsel ? 0 : ((c1 > 0.0f) ? 1 : ((c1 < 0.0f) ? -1 : 0));
        int nr = min(max(r + mr, 0), POSMAX);
        int nc = min(max(c + mc, 0), POSMAX);
        if (on) g_pos[b] = (unsigned int)nr | ((unsigned int)nc << 8);

        // coact: per-warp partials, no syncthreads, no cross-warp combine.
        // sh_s written+read by the SAME thread (legalizes dynamic index only).
#pragma unroll
        for (int u = 0; u < 15; u++) sh_s[u][tid] = on ? s[u] : 0.0f;
        int np = g_np;
        int lane = tid & 31;
        int wg = b >> 5;          // global warp id
        for (int p = 0; p < np; p++) {
            int e = sh_pp[p];
            float v = sh_s[e & 255][tid] * sh_s[e >> 8][tid];
            v = warp_sum(v);
            if (lane == 0) g_partial[p * MAXW + wg] = v;
        }
    } else {
        if (on) {
#pragma unroll
            for (int o2 = 0; o2 < 10; o2++) {
                float l = bo[o2];
#pragma unroll
                for (int u = 0; u < 15; u++) l = fmaf(s[u], Wo[o2 * 15 + u], l);
                __stcs(&out[(size_t)b * 10 + o2], l);
            }
        }
    }
}

// 1 block x 1024 threads: warp per active pair, 16 independent float4 loads
// per lane (MLP=16, one L2 round), fixed-tree reduce -> deterministic.
__global__ void reff_kernel(const float* __restrict__ R, const float* __restrict__ mask,
                            int B, int NW) {
    int wid = threadIdx.x >> 5, lane = threadIdx.x & 31;
    int np = g_np;
    int n4 = NW >> 2;
    for (int p = wid; p < np; p += 32) {
        const float4* s4 = (const float4*)(g_partial + p * MAXW);
        float a = 0.0f;
#pragma unroll 16
        for (int t = lane; t < n4; t += 32) {
            float4 v = s4[t];
            a += (v.x + v.y) + (v.z + v.w);
        }
        a = warp_sum(a);
        if (lane == 0) {
            int idx = g_pidx[p];
            int i = idx / 15, j = idx % 15;
            g_reffT[j * 16 + i] = (R[idx] - LAM * (a / (float)B)) * mask[idx];
        }
    }
}

extern "C" void kernel_launch(void* const* d_in, const int* in_sizes, int n_in,
                              void* d_out, int out_size) {
    const float* x     = (const float*)d_in[0];
    const float* Wi    = (const float*)d_in[1];
    const float* bi    = (const float*)d_in[2];
    const float* gamma = (const float*)d_in[3];
    const float* beta  = (const float*)d_in[4];
    const float* R     = (const float*)d_in[5];
    const float* rb    = (const float*)d_in[6];
    const float* mask  = (const float*)d_in[7];
    const float* Wc    = (const float*)d_in[8];
    const float* bc    = (const float*)d_in[9];
    const float* Wo    = (const float*)d_in[10];
    const float* bo    = (const float*)d_in[11];
    float* out = (float*)d_out;

    int B = in_sizes[0] / (IM * IM);
    if (B > MAXB) B = MAXB;
    int nblk = (B + TPB - 1) / TPB;
    int NW = nblk * (TPB / 32);
    int pblk = (B * 80 + 255) / 256;

    prep_kernel<<<1, 256>>>(Wi, mask);
    pack_kernel<<<pblk, 256>>>(x, B);
    step_kernel<0><<<nblk, TPB>>>(bi, gamma, beta, rb, Wc, bc, Wo, bo, out, B, NW);
    reff_kernel<<<1, 1024>>>(R, mask, B, NW);
    step_kernel<1><<<nblk, TPB>>>(bi, gamma, beta, rb, Wc, bc, Wo, bo, out, B, NW);
    reff_kernel<<<1, 1024>>>(R, mask, B, NW);
    step_kernel<1><<<nblk, TPB>>>(bi, gamma, beta, rb, Wc, bc, Wo, bo, out, B, NW);
    reff_kernel<<<1, 1024>>>(R, mask, B, NW);
    step_kernel<1><<<nblk, TPB>>>(bi, gamma, beta, rb, Wc, bc, Wo, bo, out, B, NW);
    reff_kernel<<<1, 1024>>>(R, mask, B, NW);
    step_kernel<2><<<nblk, TPB>>>(bi, gamma, beta, rb, Wc, bc, Wo, bo, out, B, NW);
}

// round 14
// speedup vs baseline: 1.9089x; 1.1545x over previous
#include <cuda_runtime.h>

#define BAG 15
#define IM 28
#define POSMAX 20
#define LAM 0.001f
#define TPB 128
#define MAXB 65536
#define MAXW (MAXB / 32)   /* 2048 warps max */
#define NPMAX 225

__device__ __align__(16) float g_WiT[66 * 16];   // WiT[k*16+u] = Wi[u*66+k], col 15 = 0
__device__ __align__(16) float g_reffT[16 * 16]; // [j*16+u] = Reff[u][j]
__device__ float g_state[BAG * MAXB];            // [u][b]
__device__ unsigned int g_pos[MAXB];             // r | (c<<8)
__device__ float g_partial[NPMAX * MAXW];        // [pair][warp] partial sums (1.8MB)
__device__ int g_pidx[NPMAX];                    // flattened mask index of active pairs
__device__ int g_pij[NPMAX];                     // i | (j<<8)
__device__ int g_np;
__device__ unsigned int g_ctr;                   // last-block counter

__device__ __forceinline__ float warp_sum(float v) {
    v += __shfl_xor_sync(0xffffffffu, v, 16);
    v += __shfl_xor_sync(0xffffffffu, v, 8);
    v += __shfl_xor_sync(0xffffffffu, v, 4);
    v += __shfl_xor_sync(0xffffffffu, v, 2);
    v += __shfl_xor_sync(0xffffffffu, v, 1);
    return v;
}

// acc[0..14] += val * base[0..14]   (base 16B-aligned shared, padded to 16 floats)
#define FMA15S(val, base) do {                                             \
    const float4* _wp = (const float4*)(base);                             \
    float4 _w0 = _wp[0], _w1 = _wp[1], _w2 = _wp[2], _w3 = _wp[3];         \
    float _v = (val);                                                      \
    acc[0]  = fmaf(_v, _w0.x, acc[0]);  acc[1]  = fmaf(_v, _w0.y, acc[1]); \
    acc[2]  = fmaf(_v, _w0.z, acc[2]);  acc[3]  = fmaf(_v, _w0.w, acc[3]); \
    acc[4]  = fmaf(_v, _w1.x, acc[4]);  acc[5]  = fmaf(_v, _w1.y, acc[5]); \
    acc[6]  = fmaf(_v, _w1.z, acc[6]);  acc[7]  = fmaf(_v, _w1.w, acc[7]); \
    acc[8]  = fmaf(_v, _w2.x, acc[8]);  acc[9]  = fmaf(_v, _w2.y, acc[9]); \
    acc[10] = fmaf(_v, _w2.z, acc[10]); acc[11] = fmaf(_v, _w2.w, acc[11]);\
    acc[12] = fmaf(_v, _w3.x, acc[12]); acc[13] = fmaf(_v, _w3.y, acc[13]);\
    acc[14] = fmaf(_v, _w3.z, acc[14]);                                    \
} while (0)

__global__ void prep_kernel(const float* __restrict__ Wi, const float* __restrict__ mask) {
    int t = threadIdx.x;
    for (int idx = t; idx < 66 * 16; idx += 256) {
        int k = idx >> 4, u = idx & 15;
        g_WiT[idx] = (u < 15) ? Wi[u * 66 + k] : 0.0f;
    }
    for (int idx = t; idx < 256; idx += 256) g_reffT[idx] = 0.0f;
    if (t == 0) {
        g_ctr = 0;
        int np = 0;
        for (int idx = 0; idx < 225; idx++) {
            if (mask[idx] != 0.0f) {
                g_pidx[np] = idx;
                g_pij[np] = (idx / 15) | ((idx % 15) << 8);
                np++;
            }
        }
        g_np = np;
    }
}

// MODE 0: first step (fixed pos (10,10), no recurrent) + fused reff reduce.
// MODE 1: middle (recurrent) + fused reff reduce. MODE 2: last (logits only).
template <int MODE>
__global__ __launch_bounds__(TPB, 6) void step_kernel(
    const float* __restrict__ x,
    const float* __restrict__ bi, const float* __restrict__ gamma,
    const float* __restrict__ beta, const float* __restrict__ rb,
    const float* __restrict__ Wc, const float* __restrict__ bc,
    const float* __restrict__ Wo, const float* __restrict__ bo,
    const float* __restrict__ R, const float* __restrict__ mask,
    float* __restrict__ out, int B)
{
    __shared__ __align__(16) float sh_wi[66 * 16];
    __shared__ __align__(16) float sh_rf[16 * 16];
    __shared__ float sh_s[BAG][TPB];
    __shared__ int sh_pp[NPMAX];
    __shared__ unsigned int sh_last;

    int tid = threadIdx.x;
    int b = blockIdx.x * TPB + tid;
    int bb = (b < B) ? b : 0;
    bool on = (b < B);

    // issue position + state loads first (one overlapped latency window)
    int r, c;
    if (MODE == 0) { r = 10; c = 10; }
    else { unsigned int p = g_pos[bb]; r = (int)(p & 255u); c = (int)(p >> 8); }
    float st[15];
    if (MODE) {
#pragma unroll
        for (int j = 0; j < 15; j++) st[j] = g_state[j * MAXB + bb];
    }

    // stage weights (and pair list) into shared
    {
        const float4* s = (const float4*)g_WiT;
        float4* d = (float4*)sh_wi;
        for (int i = tid; i < 264; i += TPB) d[i] = s[i];
        if (MODE) {
            const float4* s2 = (const float4*)g_reffT;
            float4* d2 = (float4*)sh_rf;
            if (tid < 64) d2[tid] = s2[tid];
        }
        if (MODE < 2)
            for (int i = tid; i < NPMAX; i += TPB) sh_pp[i] = g_pij[i];
    }
    __syncthreads();

    float acc[15];
#pragma unroll
    for (int u = 0; u < 15; u++) acc[u] = bi[u] + (MODE ? rb[u] : 0.0f);

    if (MODE) {
#pragma unroll
        for (int j = 0; j < 15; j++) FMA15S(st[j], sh_rf + j * 16);
        float pr = (float)r * (2.0f / (float)POSMAX) - 1.0f;
        float pc = (float)c * (2.0f / (float)POSMAX) - 1.0f;
        FMA15S(pr, sh_wi + 64 * 16);
        FMA15S(pc, sh_wi + 65 * 16);
    }
    // MODE 0: pos terms are (10/20*2-1) = 0 -> skip entirely.

    // ---- 8x8 patch straight from x: 3 aligned float4 per row + SEL shift ----
    // r,c in [6,14] always (start (10,10), <=4 unit moves) -> in-bounds.
    {
        int cb = c & ~3;          // in {4,8,12}
        int sh = c & 3;
        const float* img = x + (size_t)bb * (IM * IM) + cb;
        bool s2 = (sh & 2) != 0;
        bool s1 = (sh & 1) != 0;
#pragma unroll
        for (int i = 0; i < 8; i++) {
            const float4* rp = (const float4*)(img + (r + i) * IM);
            float4 a0 = rp[0];
            float4 a1 = rp[1];
            float4 a2 = rp[2];
            float v0 = a0.x, v1 = a0.y, v2 = a0.z, v3 = a0.w;
            float v4 = a1.x, v5 = a1.y, v6 = a1.z, v7 = a1.w;
            float v8 = a2.x, v9 = a2.y, v10 = a2.z;
            float t0 = s2 ? v2 : v0, t1 = s2 ? v3 : v1, t2 = s2 ? v4 : v2;
            float t3 = s2 ? v5 : v3, t4 = s2 ? v6 : v4, t5 = s2 ? v7 : v5;
            float t6 = s2 ? v8 : v6, t7 = s2 ? v9 : v7, t8 = s2 ? v10 : v8;
            float f0 = s1 ? t1 : t0, f1 = s1 ? t2 : t1, f2 = s1 ? t3 : t2;
            float f3 = s1 ? t4 : t3, f4 = s1 ? t5 : t4, f5 = s1 ? t6 : t5;
            float f6 = s1 ? t7 : t6, f7 = s1 ? t8 : t7;
            FMA15S(f0, sh_wi + (i * 8 + 0) * 16);
            FMA15S(f1, sh_wi + (i * 8 + 1) * 16);
            FMA15S(f2, sh_wi + (i * 8 + 2) * 16);
            FMA15S(f3, sh_wi + (i * 8 + 3) * 16);
            FMA15S(f4, sh_wi + (i * 8 + 4) * 16);
            FMA15S(f5, sh_wi + (i * 8 + 5) * 16);
            FMA15S(f6, sh_wi + (i * 8 + 6) * 16);
            FMA15S(f7, sh_wi + (i * 8 + 7) * 16);
        }
    }

    // ---- relu + layernorm ----
    float mu = 0.0f;
#pragma unroll
    for (int u = 0; u < 15; u++) { acc[u] = fmaxf(acc[u], 0.0f); mu += acc[u]; }
    mu *= (1.0f / 15.0f);
    float var = 0.0f;
#pragma unroll
    for (int u = 0; u < 15; u++) { float d = acc[u] - mu; acc[u] = d; var += d * d; }
    var *= (1.0f / 15.0f);
    float inv = rsqrtf(var + 1e-5f);
    float s[15];
#pragma unroll
    for (int u = 0; u < 15; u++) s[u] = acc[u] * inv * gamma[u] + beta[u];

    if (MODE < 2) {
        if (on) {
#pragma unroll
            for (int u = 0; u < 15; u++) g_state[u * MAXB + b] = s[u];
        }
        // control head (tanh skipped: odd + strictly monotone, decisions identical)
        float c0 = bc[0], c1 = bc[1];
#pragma unroll
        for (int u = 0; u < 15; u++) {
            c0 = fmaf(s[u], Wc[u], c0);
            c1 = fmaf(s[u], Wc[15 + u], c1);
        }
        bool rsel = fabsf(c0) >= fabsf(c1);
        int mr = rsel ? ((c0 > 0.0f) ? 1 : ((c0 < 0.0f) ? -1 : 0)) : 0;
        int mc = rsel ? 0 : ((c1 > 0.0f) ? 1 : ((c1 < 0.0f) ? -1 : 0));
        int nr = min(max(r + mr, 0), POSMAX);
        int nc = min(max(c + mc, 0), POSMAX);
        if (on) g_pos[b] = (unsigned int)nr | ((unsigned int)nc << 8);

        // coact: per-warp partials (no cross-warp combine).
        // sh_s written+read by the SAME thread (legalizes dynamic index only).
#pragma unroll
        for (int u = 0; u < 15; u++) sh_s[u][tid] = on ? s[u] : 0.0f;
        int np = g_np;
        int lane = tid & 31;
        int wg = b >> 5;          // global warp id
        for (int p = 0; p < np; p++) {
            int e = sh_pp[p];
            float v = sh_s[e & 255][tid] * sh_s[e >> 8][tid];
            v = warp_sum(v);
            if (lane == 0) g_partial[p * MAXW + wg] = v;
        }

        // ---- fused reff: last block reduces partials into g_reffT ----
        __threadfence();
        if (tid == 0)
            sh_last = (atomicAdd(&g_ctr, 1u) == (unsigned)(gridDim.x - 1)) ? 1u : 0u;
        __syncthreads();
        if (sh_last) {
            int NW = gridDim.x * (TPB / 32);
            int n4 = NW >> 2;
            int wid = tid >> 5;
            for (int p = wid; p < np; p += (TPB / 32)) {
                const float4* s4 = (const float4*)(g_partial + p * MAXW);
                float a = 0.0f;
                for (int t = lane; t < n4; t += 32) {
                    float4 v = s4[t];
                    a += (v.x + v.y) + (v.z + v.w);
                }
                a = warp_sum(a);
                if (lane == 0) {
                    int idx = g_pidx[p];
                    int i = idx / 15, j = idx % 15;
                    g_reffT[j * 16 + i] = (R[idx] - LAM * (a / (float)B)) * mask[idx];
                }
            }
            __syncthreads();
            if (tid == 0) g_ctr = 0;
        }
    } else {
        if (on) {
#pragma unroll
            for (int o2 = 0; o2 < 10; o2++) {
                float l = bo[o2];
#pragma unroll
                for (int u = 0; u < 15; u++) l = fmaf(s[u], Wo[o2 * 15 + u], l);
                __stcs(&out[(size_t)b * 10 + o2], l);
            }
        }
    }
}

extern "C" void kernel_launch(void* const* d_in, const int* in_sizes, int n_in,
                              void* d_out, int out_size) {
    const float* x     = (const float*)d_in[0];
    const float* Wi    = (const float*)d_in[1];
    const float* bi    = (const float*)d_in[2];
    const float* gamma = (const float*)d_in[3];
    const float* beta  = (const float*)d_in[4];
    const float* R     = (const float*)d_in[5];
    const float* rb    = (const float*)d_in[6];
    const float* mask  = (const float*)d_in[7];
    const float* Wc    = (const float*)d_in[8];
    const float* bc    = (const float*)d_in[9];
    const float* Wo    = (const float*)d_in[10];
    const float* bo    = (const float*)d_in[11];
    float* out = (float*)d_out;

    int B = in_sizes[0] / (IM * IM);
    if (B > MAXB) B = MAXB;
    int nblk = (B + TPB - 1) / TPB;

    prep_kernel<<<1, 256>>>(Wi, mask);
    step_kernel<0><<<nblk, TPB>>>(x, bi, gamma, beta, rb, Wc, bc, Wo, bo, R, mask, out, B);
    step_kernel<1><<<nblk, TPB>>>(x, bi, gamma, beta, rb, Wc, bc, Wo, bo, R, mask, out, B);
    step_kernel<1><<<nblk, TPB>>>(x, bi, gamma, beta, rb, Wc, bc, Wo, bo, R, mask, out, B);
    step_kernel<1><<<nblk, TPB>>>(x, bi, gamma, beta, rb, Wc, bc, Wo, bo, R, mask, out, B);
    step_kernel<2><<<nblk, TPB>>>(x, bi, gamma, beta, rb, Wc, bc, Wo, bo, R, mask, out, B);
}